// round 10
// baseline (speedup 1.0000x reference)
#include <cuda_runtime.h>
#include <cuda_fp16.h>
#include <math.h>

#define MAX_NODES 50000
#define MAX_RELS  16

typedef unsigned long long ull;

// Scratch (device globals; no allocation allowed)
__device__ __align__(16) __half g_Ph[MAX_NODES * 128];   // [n][o][b] halves
__device__ __align__(16) __half g_uh[MAX_NODES * 32];    // init_fea @ A_w[0:32]
__device__ __align__(16) __half g_vh[MAX_NODES * 32];    // init_fea @ A_w[32:64]
__device__ __align__(16) float  g_agg[MAX_NODES * 32];   // curr + scatter of a*msg
__device__ __align__(16) float  g_t[MAX_RELS * 32];      // attn_emb @ A_w[64:96]+A_b

// ---- packed f32x2 helpers (sm_103a FFMA2 path) ----
__device__ __forceinline__ ull pk2(float lo, float hi) {
    ull r; asm("mov.b64 %0, {%1, %2};" : "=l"(r) : "f"(lo), "f"(hi)); return r;
}
__device__ __forceinline__ float2 upk(ull v) {
    float2 r; asm("mov.b64 {%0, %1}, %2;" : "=f"(r.x), "=f"(r.y) : "l"(v)); return r;
}
__device__ __forceinline__ ull fma2(ull a, ull b, ull c) {
    ull d; asm("fma.rn.f32x2 %0, %1, %2, %3;" : "=l"(d) : "l"(a), "l"(b), "l"(c));
    return d;
}

// ---------------------------------------------------------------------------
// K1: node stage, FFMA2-packed. 8 nodes/warp-task: lane = (half, h);
// half in {0,1} covers nodes {0-3, 4-7}; lane h computes output-col pair
// (2h, 2h+1) held in f32x2 accumulators. Weights packed in smem as
// wp[table][kpair][h] = (w[k][2h], w[k][2h+1], w[k+1][2h], w[k+1][2h+1]).
// Features staged duplicated so LDS gives packed multiplicands directly.
// Block 0 also builds g_t. Persistent grid-stride.
// ---------------------------------------------------------------------------
__global__ void __launch_bounds__(256) k_node(
    const float* __restrict__ feat, const float* __restrict__ embed,
    const int* __restrict__ idx, const float* __restrict__ transform,
    const float* __restrict__ weight, const float* __restrict__ A_w,
    const float* __restrict__ selfw, const float* __restrict__ attn_emb,
    const float* __restrict__ A_b, float* __restrict__ out, int n_nodes) {
    // 9 tables: 0-1 transform halves, 2-5 bases, 6-7 A_w halves, 8 selfloop
    __shared__ __align__(16) ulonglong2 wp[9][16][16];   // 36 KB
    __shared__ __align__(16) ulonglong2 sF[8][8][16];    // 16 KB, per-warp
    __shared__ __align__(16) ulonglong2 sG[8][8][16];    // 16 KB, per-warp

    int tid = threadIdx.x;

    // folded k_rel_t: t[r][o] = A_b[o] + sum_k attn_emb[r,k] * A_w[64+k, o]
    if (blockIdx.x == 0) {
        int r0 = tid >> 5;
        int o = tid & 31;
#pragma unroll
        for (int rr = 0; rr < 2; rr++) {
            int r = r0 + rr * 8;
            float acc = A_b[o];
#pragma unroll
            for (int k = 0; k < 32; k++)
                acc += attn_emb[r * 32 + k] * A_w[(64 + k) * 32 + o];
            g_t[r * 32 + o] = acc;
        }
    }

    // pack weight tables: gmem [k][o] -> wp[t][k>>1][o>>1] comp (k&1)*2+(o&1)
    {
        float* wpf = reinterpret_cast<float*>(wp);
        for (int i = tid; i < 9 * 1024; i += 256) {
            int t = i >> 10, r = i & 1023;
            int k = r >> 5, o = r & 31;
            float v;
            if (t == 0)      v = transform[r];
            else if (t == 1) v = transform[1024 + r];
            else if (t < 6)  v = weight[(t - 2) * 1024 + r];
            else if (t == 6) v = A_w[r];
            else if (t == 7) v = A_w[1024 + r];
            else             v = selfw[r];
            wpf[(t * 256 + (k >> 1) * 16 + (o >> 1)) * 4 + (k & 1) * 2 + (o & 1)] = v;
        }
    }
    __syncthreads();

    int lane = tid & 31;
    int w = tid >> 5;
    int h = lane & 15;
    int half = lane >> 4;
    int warps_per_grid = gridDim.x * 8;
    int warp0 = blockIdx.x * 8 + w;
    int n_tasks = (n_nodes + 7) >> 3;                 // warp-tasks of 8 nodes

    for (int task = warp0; task < n_tasks; task += warps_per_grid) {
        int n0 = task * 8;

        // stage f,g duplicated: lane's k = lane; ull index == lane
#pragma unroll
        for (int j = 0; j < 8; j++) {
            int n = n0 + j;
            float fj = 0.f, gj = 0.f;
            if (n < n_nodes) {
                fj = feat[n * 32 + lane];
                gj = embed[(long)idx[n] * 32 + lane];
            }
            reinterpret_cast<ull*>(&sF[w][j][0])[lane] = pk2(fj, fj);
            reinterpret_cast<ull*>(&sG[w][j][0])[lane] = pk2(gj, gj);
        }
        __syncwarp();

        // Phase A: init_fea col-pair per lane
        ull fea2[4] = {0ull, 0ull, 0ull, 0ull};
#pragma unroll 4
        for (int kp = 0; kp < 16; kp++) {
            ulonglong2 t1 = wp[0][kp][h];
            ulonglong2 t2 = wp[1][kp][h];
#pragma unroll
            for (int j = 0; j < 4; j++) {
                int jj = half * 4 + j;
                ulonglong2 fd = sF[w][jj][kp];
                ulonglong2 gd = sG[w][jj][kp];
                fea2[j] = fma2(fd.x, t1.x, fea2[j]);
                fea2[j] = fma2(fd.y, t1.y, fea2[j]);
                fea2[j] = fma2(gd.x, t2.x, fea2[j]);
                fea2[j] = fma2(gd.y, t2.y, fea2[j]);
            }
        }
        __syncwarp();   // done reading sF before overwrite with fea

        // store out[:,0,:] and stage fea duplicated (kpair h <- col pair 2h,2h+1)
#pragma unroll
        for (int j = 0; j < 4; j++) {
            int jj = half * 4 + j;
            int n = n0 + jj;
            float2 f2 = upk(fea2[j]);
            if (n < n_nodes)
                *reinterpret_cast<float2*>(&out[(long)n * 64 + 2 * h]) = f2;
            ulonglong2 d;
            d.x = pk2(f2.x, f2.x);
            d.y = pk2(f2.y, f2.y);
            sF[w][jj][h] = d;
        }
        __syncwarp();

        // Phase B: 7 packed projections
        ull P0[4] = {0,0,0,0}, P1[4] = {0,0,0,0};
        ull P2[4] = {0,0,0,0}, P3[4] = {0,0,0,0};
        ull uA[4] = {0,0,0,0}, vA[4] = {0,0,0,0}, cA[4] = {0,0,0,0};
#pragma unroll 4
        for (int kp = 0; kp < 16; kp++) {
            ulonglong2 w0 = wp[2][kp][h];
            ulonglong2 w1 = wp[3][kp][h];
            ulonglong2 w2 = wp[4][kp][h];
            ulonglong2 w3 = wp[5][kp][h];
            ulonglong2 au = wp[6][kp][h];
            ulonglong2 av = wp[7][kp][h];
            ulonglong2 ac = wp[8][kp][h];
#pragma unroll
            for (int j = 0; j < 4; j++) {
                ulonglong2 s = sF[w][half * 4 + j][kp];
                P0[j] = fma2(s.x, w0.x, P0[j]); P0[j] = fma2(s.y, w0.y, P0[j]);
                P1[j] = fma2(s.x, w1.x, P1[j]); P1[j] = fma2(s.y, w1.y, P1[j]);
                P2[j] = fma2(s.x, w2.x, P2[j]); P2[j] = fma2(s.y, w2.y, P2[j]);
                P3[j] = fma2(s.x, w3.x, P3[j]); P3[j] = fma2(s.y, w3.y, P3[j]);
                uA[j] = fma2(s.x, au.x, uA[j]); uA[j] = fma2(s.y, au.y, uA[j]);
                vA[j] = fma2(s.x, av.x, vA[j]); vA[j] = fma2(s.y, av.y, vA[j]);
                cA[j] = fma2(s.x, ac.x, cA[j]); cA[j] = fma2(s.y, ac.y, cA[j]);
            }
        }

        // Epilogue
#pragma unroll
        for (int j = 0; j < 4; j++) {
            int n = n0 + half * 4 + j;
            if (n >= n_nodes) continue;
            float2 p0 = upk(P0[j]), p1 = upk(P1[j]);
            float2 p2 = upk(P2[j]), p3 = upk(P3[j]);
            __half2 h0 = __floats2half2_rn(p0.x, p1.x);
            __half2 h1 = __floats2half2_rn(p2.x, p3.x);
            __half2 h2 = __floats2half2_rn(p0.y, p1.y);
            __half2 h3 = __floats2half2_rn(p2.y, p3.y);
            uint4 ph;
            ph.x = *reinterpret_cast<unsigned*>(&h0);
            ph.y = *reinterpret_cast<unsigned*>(&h1);
            ph.z = *reinterpret_cast<unsigned*>(&h2);
            ph.w = *reinterpret_cast<unsigned*>(&h3);
            *reinterpret_cast<uint4*>(&g_Ph[(size_t)n * 128 + h * 8]) = ph;

            float2 uu = upk(uA[j]);
            float2 vv = upk(vA[j]);
            float2 cc = upk(cA[j]);
            __half2 hu = __floats2half2_rn(uu.x, uu.y);
            __half2 hv = __floats2half2_rn(vv.x, vv.y);
            reinterpret_cast<__half2*>(g_uh)[(size_t)n * 16 + h] = hu;
            reinterpret_cast<__half2*>(g_vh)[(size_t)n * 16 + h] = hv;
            *reinterpret_cast<float2*>(&g_agg[(size_t)n * 32 + 2 * h]) = cc;
        }
        __syncwarp();   // protect sF reuse across iterations
    }
}

// ---------------------------------------------------------------------------
// K2: edge stage. 8 edges per warp (two quads, unrolled x2 for MLP);
// 8 lanes per edge; each lane covers 4 output columns.
// ---------------------------------------------------------------------------
__global__ void __launch_bounds__(256) k_edge(
    const int* __restrict__ esrc, const int* __restrict__ edst,
    const int* __restrict__ etype, const float* __restrict__ w_comp,
    const float* __restrict__ B_w, const float* __restrict__ B_b, int n_edges) {
    __shared__ __align__(16) float4 s_wc[MAX_RELS];      // w_comp per rel
    __shared__ __align__(16) float4 s_t4[MAX_RELS * 8];  // attn bias per rel
    __shared__ __align__(16) float4 s_bw4[8];
    __shared__ float s_bb;

    int tid = threadIdx.x;
    if (tid < MAX_RELS)
        s_wc[tid] = reinterpret_cast<const float4*>(w_comp)[tid];
    if (tid < MAX_RELS * 8)
        s_t4[tid] = reinterpret_cast<const float4*>(g_t)[tid];
    if (tid < 8)
        s_bw4[tid] = reinterpret_cast<const float4*>(B_w)[tid];
    if (tid == 0) s_bb = B_b[0];
    __syncthreads();

    int warp = (blockIdx.x * blockDim.x + tid) >> 5;
    int lane = tid & 31;
    int sub = lane >> 3;   // quad slot (0..3)
    int g = lane & 7;      // lane within 8-lane edge group; outputs 4g..4g+3
    float4 bw = s_bw4[g];

    int e[2];
    e[0] = warp * 8 + sub;
    e[1] = e[0] + 4;

    int src[2], dst[2], ty[2];
    bool ok[2];
#pragma unroll
    for (int q = 0; q < 2; q++) {
        ok[q] = (e[q] < n_edges);
        int ee = ok[q] ? e[q] : 0;
        src[q] = esrc[ee];
        dst[q] = edst[ee];
        ty[q] = etype[ee];
    }
    if (!ok[0]) return;

    // Issue all gathers for both edges before consuming (deep MLP)
    uint4 r0[2], r1[2];
    uint2 uu[2], vv[2];
#pragma unroll
    for (int q = 0; q < 2; q++) {
        const uint4* Pp =
            reinterpret_cast<const uint4*>(g_Ph + (size_t)src[q] * 128 + g * 16);
        r0[q] = Pp[0];
        r1[q] = Pp[1];
        uu[q] = *reinterpret_cast<const uint2*>(g_uh + (size_t)src[q] * 32 + g * 4);
        vv[q] = *reinterpret_cast<const uint2*>(g_vh + (size_t)dst[q] * 32 + g * 4);
    }

#pragma unroll
    for (int q = 0; q < 2; q++) {
        if (!ok[q]) break;
        float4 cc = s_wc[ty[q]];
        float4 t4 = s_t4[ty[q] * 8 + g];

        float2 p00 = __half22float2(*reinterpret_cast<__half2*>(&r0[q].x));
        float2 p01 = __half22float2(*reinterpret_cast<__half2*>(&r0[q].y));
        float2 p10 = __half22float2(*reinterpret_cast<__half2*>(&r0[q].z));
        float2 p11 = __half22float2(*reinterpret_cast<__half2*>(&r0[q].w));
        float2 p20 = __half22float2(*reinterpret_cast<__half2*>(&r1[q].x));
        float2 p21 = __half22float2(*reinterpret_cast<__half2*>(&r1[q].y));
        float2 p30 = __half22float2(*reinterpret_cast<__half2*>(&r1[q].z));
        float2 p31 = __half22float2(*reinterpret_cast<__half2*>(&r1[q].w));

        float4 msg;
        msg.x = p00.x * cc.x + p00.y * cc.y + p01.x * cc.z + p01.y * cc.w;
        msg.y = p10.x * cc.x + p10.y * cc.y + p11.x * cc.z + p11.y * cc.w;
        msg.z = p20.x * cc.x + p20.y * cc.y + p21.x * cc.z + p21.y * cc.w;
        msg.w = p30.x * cc.x + p30.y * cc.y + p31.x * cc.z + p31.y * cc.w;

        float2 u0 = __half22float2(*reinterpret_cast<__half2*>(&uu[q].x));
        float2 u1 = __half22float2(*reinterpret_cast<__half2*>(&uu[q].y));
        float2 v0 = __half22float2(*reinterpret_cast<__half2*>(&vv[q].x));
        float2 v1 = __half22float2(*reinterpret_cast<__half2*>(&vv[q].y));

        float zx = fmaxf(u0.x + v0.x + t4.x, 0.f);
        float zy = fmaxf(u0.y + v0.y + t4.y, 0.f);
        float zz = fmaxf(u1.x + v1.x + t4.z, 0.f);
        float zw = fmaxf(u1.y + v1.y + t4.w, 0.f);

        float s = zx * bw.x + zy * bw.y + zz * bw.z + zw * bw.w;
        s += __shfl_xor_sync(0xffffffffu, s, 4);
        s += __shfl_xor_sync(0xffffffffu, s, 2);
        s += __shfl_xor_sync(0xffffffffu, s, 1);
        float a = 1.f / (1.f + __expf(-(s + s_bb)));

        float4 r = make_float4(a * msg.x, a * msg.y, a * msg.z, a * msg.w);
        atomicAdd(reinterpret_cast<float4*>(g_agg) + (size_t)dst[q] * 8 + g, r);
    }
}

// ---------------------------------------------------------------------------
// K3: h = relu(agg) -> out[:,1,:]  (float4 vectorized)
// ---------------------------------------------------------------------------
__global__ void k_final(float* __restrict__ out, int n4) {
    int i = blockIdx.x * blockDim.x + threadIdx.x;   // over n_nodes*8 float4s
    if (i >= n4) return;
    int n = i >> 3;
    int q = i & 7;
    float4 v = reinterpret_cast<const float4*>(g_agg)[i];
    float4 r = make_float4(fmaxf(v.x, 0.f), fmaxf(v.y, 0.f),
                           fmaxf(v.z, 0.f), fmaxf(v.w, 0.f));
    reinterpret_cast<float4*>(out)[(size_t)n * 16 + 8 + q] = r;
}

extern "C" void kernel_launch(void* const* d_in, const int* in_sizes, int n_in,
                              void* d_out, int out_size) {
    const float* feat      = (const float*)d_in[0];
    const float* embed     = (const float*)d_in[1];
    const float* transform = (const float*)d_in[2];
    const float* weight    = (const float*)d_in[3];
    const float* w_comp    = (const float*)d_in[4];
    const float* selfw     = (const float*)d_in[5];
    const float* A_w       = (const float*)d_in[6];
    const float* A_b       = (const float*)d_in[7];
    const float* B_w       = (const float*)d_in[8];
    const float* B_b       = (const float*)d_in[9];
    const float* attn_emb  = (const float*)d_in[10];
    const int*   idx       = (const int*)d_in[11];
    const int*   esrc      = (const int*)d_in[12];
    const int*   edst      = (const int*)d_in[13];
    const int*   ety       = (const int*)d_in[14];
    float* out = (float*)d_out;

    int n_nodes = in_sizes[0] / 32;
    int n_edges = in_sizes[12];

    int blocks1 = 296;   // persistent, ~2 blocks/SM
    k_node<<<blocks1, 256>>>(feat, embed, idx, transform, weight, A_w, selfw,
                             attn_emb, A_b, out, n_nodes);

    int blocks2 = (n_edges + 63) / 64;  // 8 warps/block, 8 edges/warp
    k_edge<<<blocks2, 256>>>(esrc, edst, ety, w_comp, B_w, B_b, n_edges);

    int n4 = n_nodes * 8;
    int blocks3 = (n4 + 255) / 256;
    k_final<<<blocks3, 256>>>(out, n4);
}

// round 11
// speedup vs baseline: 1.3271x; 1.3271x over previous
#include <cuda_runtime.h>
#include <cuda_fp16.h>
#include <math.h>

#define MAX_NODES 50000
#define MAX_RELS  16

// Scratch (device globals; no allocation allowed)
// g_Ph layout: [n][basis t][col] halves  (128 halves per node)
__device__ __align__(16) __half g_Ph[MAX_NODES * 128];
__device__ __align__(16) __half g_uh[MAX_NODES * 32];    // [n][col]
__device__ __align__(16) __half g_vh[MAX_NODES * 32];    // [n][col]
__device__ __align__(16) float  g_agg[MAX_NODES * 32];   // curr + scatter
__device__ __align__(16) float  g_t[MAX_RELS * 32];      // attn bias table

__device__ __forceinline__ float tf32r(float x) {
    unsigned r;
    asm("cvt.rna.tf32.f32 %0, %1;" : "=r"(r) : "f"(x));
    return __uint_as_float(r);
}
__device__ __forceinline__ unsigned f2u(float x) { return __float_as_uint(x); }

__device__ __forceinline__ void mma_tf32(
    float* d, unsigned a0, unsigned a1, unsigned a2, unsigned a3,
    unsigned b0, unsigned b1) {
    asm("mma.sync.aligned.m16n8k8.row.col.f32.tf32.tf32.f32 "
        "{%0,%1,%2,%3},{%4,%5,%6,%7},{%8,%9},{%0,%1,%2,%3};"
        : "+f"(d[0]), "+f"(d[1]), "+f"(d[2]), "+f"(d[3])
        : "r"(a0), "r"(a1), "r"(a2), "r"(a3), "r"(b0), "r"(b1));
}

// smem layout (floats): sWA [64][40] = 2560 | sWB [32][232] = 7424 |
//                       sX  [8 warps][16][68] = 8704
#define SWA_OFF 0
#define SWB_OFF 2560
#define SX_OFF  (2560 + 7424)
#define SMEM_FLOATS (2560 + 7424 + 8704)
#define SMEM_BYTES (SMEM_FLOATS * 4)

// ---------------------------------------------------------------------------
// K1: node stage via tensor cores (mma.m16n8k8.tf32). 16 nodes per warp.
// Phase A: X[16x64] @ transform[64x32] -> fea (also out[:,0,:]).
// Phase B: fea[16x32] @ Wcat[32x224] -> P0..P3, u, v, selfloop.
// Block 0 also builds g_t.
// ---------------------------------------------------------------------------
__global__ void __launch_bounds__(256) k_node(
    const float* __restrict__ feat, const float* __restrict__ embed,
    const int* __restrict__ idx, const float* __restrict__ transform,
    const float* __restrict__ weight, const float* __restrict__ A_w,
    const float* __restrict__ selfw, const float* __restrict__ attn_emb,
    const float* __restrict__ A_b, float* __restrict__ out, int n_nodes) {
    extern __shared__ float smem_dyn[];
    float* sWA = smem_dyn + SWA_OFF;
    float* sWB = smem_dyn + SWB_OFF;

    int tid = threadIdx.x;

    // g_t table (block 0): t[r][o] = A_b[o] + sum_k attn_emb[r,k]*A_w[64+k,o]
    if (blockIdx.x == 0) {
        int r0 = tid >> 5;
        int o = tid & 31;
#pragma unroll
        for (int rr = 0; rr < 2; rr++) {
            int r = r0 + rr * 8;
            float acc = A_b[o];
#pragma unroll
            for (int k = 0; k < 32; k++)
                acc += attn_emb[r * 32 + k] * A_w[(64 + k) * 32 + o];
            g_t[r * 32 + o] = acc;
        }
    }

    // stage phase-A weights: sWA[k][o], tf32-rounded, stride 40
    for (int i = tid; i < 2048; i += 256) {
        int k = i >> 5, o = i & 31;
        sWA[k * 40 + o] = tf32r(transform[i]);
    }
    // stage phase-B weights: 7 tables -> sWB[k][t*32+o], stride 232
    for (int i = tid; i < 7 * 1024; i += 256) {
        int t = i >> 10, r = i & 1023;
        int k = r >> 5, o = r & 31;
        float v;
        if (t < 4)       v = weight[t * 1024 + r];
        else if (t == 4) v = A_w[r];
        else if (t == 5) v = A_w[1024 + r];
        else             v = selfw[r];
        sWB[k * 232 + t * 32 + o] = tf32r(v);
    }
    __syncthreads();

    int lane = tid & 31;
    int w = tid >> 5;
    float* sXw = smem_dyn + SX_OFF + w * 1088;   // [16][68]

    int gid = lane >> 2;    // 0..7
    int tid4 = lane & 3;    // 0..3

    int n_tasks = (n_nodes + 15) >> 4;
    int task = blockIdx.x * 8 + w;
    if (task >= n_tasks) return;
    int n0 = task * 16;

    // ---- stage X = [feat | embed[idx]] as tf32, rows 16 x cols 64 ----
    int iIdx = 0;
    if (lane < 16 && n0 + lane < n_nodes) iIdx = idx[n0 + lane];
#pragma unroll
    for (int it = 0; it < 8; it++) {
        int r = it * 2 + (lane >> 4);   // 0..15
        int f4 = lane & 15;             // 0..15 (col group of 4)
        int n = n0 + r;
        int e = __shfl_sync(0xffffffffu, iIdx, r);
        float4 vle = make_float4(0.f, 0.f, 0.f, 0.f);
        if (n < n_nodes) {
            if (f4 < 8)
                vle = *reinterpret_cast<const float4*>(&feat[(size_t)n * 32 + f4 * 4]);
            else
                vle = *reinterpret_cast<const float4*>(&embed[(size_t)e * 32 + (f4 - 8) * 4]);
        }
        float4 tv = make_float4(tf32r(vle.x), tf32r(vle.y), tf32r(vle.z), tf32r(vle.w));
        *reinterpret_cast<float4*>(&sXw[r * 68 + f4 * 4]) = tv;
    }
    __syncwarp();

    // ---- Phase A: 8 k-steps x 4 n-tiles ----
    float accA[4][4];
#pragma unroll
    for (int nt = 0; nt < 4; nt++)
#pragma unroll
        for (int i = 0; i < 4; i++) accA[nt][i] = 0.f;

#pragma unroll
    for (int kk = 0; kk < 8; kk++) {
        int kb = kk * 8;
        unsigned a0 = f2u(sXw[gid * 68 + kb + tid4]);
        unsigned a1 = f2u(sXw[(gid + 8) * 68 + kb + tid4]);
        unsigned a2 = f2u(sXw[gid * 68 + kb + tid4 + 4]);
        unsigned a3 = f2u(sXw[(gid + 8) * 68 + kb + tid4 + 4]);
#pragma unroll
        for (int nt = 0; nt < 4; nt++) {
            unsigned b0 = f2u(sWA[(kb + tid4) * 40 + nt * 8 + gid]);
            unsigned b1 = f2u(sWA[(kb + tid4 + 4) * 40 + nt * 8 + gid]);
            mma_tf32(accA[nt], a0, a1, a2, a3, b0, b1);
        }
    }
    __syncwarp();   // all reads of sXw done before overwrite

    int n_a = n0 + gid;
    int n_b = n0 + gid + 8;
    // store out[:,0,:] (fp32) and stage fea (tf32) back into sXw
#pragma unroll
    for (int nt = 0; nt < 4; nt++) {
        int c = nt * 8 + 2 * tid4;
        if (n_a < n_nodes)
            *reinterpret_cast<float2*>(&out[(size_t)n_a * 64 + c]) =
                make_float2(accA[nt][0], accA[nt][1]);
        if (n_b < n_nodes)
            *reinterpret_cast<float2*>(&out[(size_t)n_b * 64 + c]) =
                make_float2(accA[nt][2], accA[nt][3]);
        *reinterpret_cast<float2*>(&sXw[gid * 68 + c]) =
            make_float2(tf32r(accA[nt][0]), tf32r(accA[nt][1]));
        *reinterpret_cast<float2*>(&sXw[(gid + 8) * 68 + c]) =
            make_float2(tf32r(accA[nt][2]), tf32r(accA[nt][3]));
    }
    __syncwarp();

    // ---- Phase B: A-frags for fea [16x32], 4 k-steps ----
    unsigned af[4][4];
#pragma unroll
    for (int kk = 0; kk < 4; kk++) {
        int kb = kk * 8;
        af[kk][0] = f2u(sXw[gid * 68 + kb + tid4]);
        af[kk][1] = f2u(sXw[(gid + 8) * 68 + kb + tid4]);
        af[kk][2] = f2u(sXw[gid * 68 + kb + tid4 + 4]);
        af[kk][3] = f2u(sXw[(gid + 8) * 68 + kb + tid4 + 4]);
    }

#pragma unroll
    for (int t = 0; t < 7; t++) {
#pragma unroll
        for (int s = 0; s < 4; s++) {
            int cB = (t * 4 + s) * 8;
            float d[4] = {0.f, 0.f, 0.f, 0.f};
#pragma unroll
            for (int kk = 0; kk < 4; kk++) {
                unsigned b0 = f2u(sWB[(kk * 8 + tid4) * 232 + cB + gid]);
                unsigned b1 = f2u(sWB[(kk * 8 + tid4 + 4) * 232 + cB + gid]);
                mma_tf32(d, af[kk][0], af[kk][1], af[kk][2], af[kk][3], b0, b1);
            }
            int col = s * 8 + 2 * tid4;   // col within table, even
            if (t < 4) {
                if (n_a < n_nodes)
                    *reinterpret_cast<__half2*>(&g_Ph[(size_t)n_a * 128 + t * 32 + col]) =
                        __floats2half2_rn(d[0], d[1]);
                if (n_b < n_nodes)
                    *reinterpret_cast<__half2*>(&g_Ph[(size_t)n_b * 128 + t * 32 + col]) =
                        __floats2half2_rn(d[2], d[3]);
            } else if (t == 4) {
                if (n_a < n_nodes)
                    *reinterpret_cast<__half2*>(&g_uh[(size_t)n_a * 32 + col]) =
                        __floats2half2_rn(d[0], d[1]);
                if (n_b < n_nodes)
                    *reinterpret_cast<__half2*>(&g_uh[(size_t)n_b * 32 + col]) =
                        __floats2half2_rn(d[2], d[3]);
            } else if (t == 5) {
                if (n_a < n_nodes)
                    *reinterpret_cast<__half2*>(&g_vh[(size_t)n_a * 32 + col]) =
                        __floats2half2_rn(d[0], d[1]);
                if (n_b < n_nodes)
                    *reinterpret_cast<__half2*>(&g_vh[(size_t)n_b * 32 + col]) =
                        __floats2half2_rn(d[2], d[3]);
            } else {
                if (n_a < n_nodes)
                    *reinterpret_cast<float2*>(&g_agg[(size_t)n_a * 32 + col]) =
                        make_float2(d[0], d[1]);
                if (n_b < n_nodes)
                    *reinterpret_cast<float2*>(&g_agg[(size_t)n_b * 32 + col]) =
                        make_float2(d[2], d[3]);
            }
        }
    }
}

// ---------------------------------------------------------------------------
// K2: edge stage. 8 edges per warp (two quads); 8 lanes per edge; each lane
// covers 4 output columns. g_Ph layout: [n][basis][col] halves.
// ---------------------------------------------------------------------------
__global__ void __launch_bounds__(256) k_edge(
    const int* __restrict__ esrc, const int* __restrict__ edst,
    const int* __restrict__ etype, const float* __restrict__ w_comp,
    const float* __restrict__ B_w, const float* __restrict__ B_b, int n_edges) {
    __shared__ __align__(16) float4 s_wc[MAX_RELS];
    __shared__ __align__(16) float4 s_t4[MAX_RELS * 8];
    __shared__ __align__(16) float4 s_bw4[8];
    __shared__ float s_bb;

    int tid = threadIdx.x;
    if (tid < MAX_RELS)
        s_wc[tid] = reinterpret_cast<const float4*>(w_comp)[tid];
    if (tid < MAX_RELS * 8)
        s_t4[tid] = reinterpret_cast<const float4*>(g_t)[tid];
    if (tid < 8)
        s_bw4[tid] = reinterpret_cast<const float4*>(B_w)[tid];
    if (tid == 0) s_bb = B_b[0];
    __syncthreads();

    int warp = (blockIdx.x * blockDim.x + tid) >> 5;
    int lane = tid & 31;
    int sub = lane >> 3;
    int g = lane & 7;
    float4 bw = s_bw4[g];

    int e[2];
    e[0] = warp * 8 + sub;
    e[1] = e[0] + 4;

    int src[2], dst[2], ty[2];
    bool ok[2];
#pragma unroll
    for (int q = 0; q < 2; q++) {
        ok[q] = (e[q] < n_edges);
        int ee = ok[q] ? e[q] : 0;
        src[q] = esrc[ee];
        dst[q] = edst[ee];
        ty[q] = etype[ee];
    }
    if (!ok[0]) return;

    // gathers for both edges first (deep MLP)
    uint2 rp[2][4];
    uint2 uu[2], vv[2];
#pragma unroll
    for (int q = 0; q < 2; q++) {
#pragma unroll
        for (int t = 0; t < 4; t++)
            rp[q][t] = *reinterpret_cast<const uint2*>(
                g_Ph + (size_t)src[q] * 128 + t * 32 + 4 * g);
        uu[q] = *reinterpret_cast<const uint2*>(g_uh + (size_t)src[q] * 32 + g * 4);
        vv[q] = *reinterpret_cast<const uint2*>(g_vh + (size_t)dst[q] * 32 + g * 4);
    }

#pragma unroll
    for (int q = 0; q < 2; q++) {
        if (!ok[q]) break;
        float4 cc = s_wc[ty[q]];
        float4 t4 = s_t4[ty[q] * 8 + g];

        float2 qa[4], qb[4];
#pragma unroll
        for (int t = 0; t < 4; t++) {
            qa[t] = __half22float2(*reinterpret_cast<__half2*>(&rp[q][t].x));
            qb[t] = __half22float2(*reinterpret_cast<__half2*>(&rp[q][t].y));
        }

        float4 msg;
        msg.x = qa[0].x * cc.x + qa[1].x * cc.y + qa[2].x * cc.z + qa[3].x * cc.w;
        msg.y = qa[0].y * cc.x + qa[1].y * cc.y + qa[2].y * cc.z + qa[3].y * cc.w;
        msg.z = qb[0].x * cc.x + qb[1].x * cc.y + qb[2].x * cc.z + qb[3].x * cc.w;
        msg.w = qb[0].y * cc.x + qb[1].y * cc.y + qb[2].y * cc.z + qb[3].y * cc.w;

        float2 u0 = __half22float2(*reinterpret_cast<__half2*>(&uu[q].x));
        float2 u1 = __half22float2(*reinterpret_cast<__half2*>(&uu[q].y));
        float2 v0 = __half22float2(*reinterpret_cast<__half2*>(&vv[q].x));
        float2 v1 = __half22float2(*reinterpret_cast<__half2*>(&vv[q].y));

        float zx = fmaxf(u0.x + v0.x + t4.x, 0.f);
        float zy = fmaxf(u0.y + v0.y + t4.y, 0.f);
        float zz = fmaxf(u1.x + v1.x + t4.z, 0.f);
        float zw = fmaxf(u1.y + v1.y + t4.w, 0.f);

        float s = zx * bw.x + zy * bw.y + zz * bw.z + zw * bw.w;
        s += __shfl_xor_sync(0xffffffffu, s, 4);
        s += __shfl_xor_sync(0xffffffffu, s, 2);
        s += __shfl_xor_sync(0xffffffffu, s, 1);
        float a = 1.f / (1.f + __expf(-(s + s_bb)));

        float4 r = make_float4(a * msg.x, a * msg.y, a * msg.z, a * msg.w);
        atomicAdd(reinterpret_cast<float4*>(g_agg) + (size_t)dst[q] * 8 + g, r);
    }
}

// ---------------------------------------------------------------------------
// K3: h = relu(agg) -> out[:,1,:]  (float4 vectorized)
// ---------------------------------------------------------------------------
__global__ void k_final(float* __restrict__ out, int n4) {
    int i = blockIdx.x * blockDim.x + threadIdx.x;
    if (i >= n4) return;
    int n = i >> 3;
    int q = i & 7;
    float4 v = reinterpret_cast<const float4*>(g_agg)[i];
    float4 r = make_float4(fmaxf(v.x, 0.f), fmaxf(v.y, 0.f),
                           fmaxf(v.z, 0.f), fmaxf(v.w, 0.f));
    reinterpret_cast<float4*>(out)[(size_t)n * 16 + 8 + q] = r;
}

extern "C" void kernel_launch(void* const* d_in, const int* in_sizes, int n_in,
                              void* d_out, int out_size) {
    const float* feat      = (const float*)d_in[0];
    const float* embed     = (const float*)d_in[1];
    const float* transform = (const float*)d_in[2];
    const float* weight    = (const float*)d_in[3];
    const float* w_comp    = (const float*)d_in[4];
    const float* selfw     = (const float*)d_in[5];
    const float* A_w       = (const float*)d_in[6];
    const float* A_b       = (const float*)d_in[7];
    const float* B_w       = (const float*)d_in[8];
    const float* B_b       = (const float*)d_in[9];
    const float* attn_emb  = (const float*)d_in[10];
    const int*   idx       = (const int*)d_in[11];
    const int*   esrc      = (const int*)d_in[12];
    const int*   edst      = (const int*)d_in[13];
    const int*   ety       = (const int*)d_in[14];
    float* out = (float*)d_out;

    int n_nodes = in_sizes[0] / 32;
    int n_edges = in_sizes[12];

    cudaFuncSetAttribute(k_node, cudaFuncAttributeMaxDynamicSharedMemorySize,
                         SMEM_BYTES);

    int n_tasks = (n_nodes + 15) / 16;
    int blocks1 = (n_tasks + 7) / 8;
    k_node<<<blocks1, 256, SMEM_BYTES>>>(feat, embed, idx, transform, weight,
                                         A_w, selfw, attn_emb, A_b, out,
                                         n_nodes);

    int blocks2 = (n_edges + 63) / 64;
    k_edge<<<blocks2, 256>>>(esrc, edst, ety, w_comp, B_w, B_b, n_edges);

    int n4 = n_nodes * 8;
    int blocks3 = (n4 + 255) / 256;
    k_final<<<blocks3, 256>>>(out, n4);
}